// round 1
// baseline (speedup 1.0000x reference)
#include <cuda_runtime.h>
#include <cuda_bf16.h>

#define IN_F   4096
#define OUT_F  4096
#define RANK   8
#define MAX_TOKENS 8192

// Intermediate t[tok][r] = x @ core1^T  (256 KB, lives in L2)
__device__ float g_t[MAX_TOKENS * RANK];

// ---------------------------------------------------------------------------
// Stage 1: t[tok, r] = sum_i x[tok, i] * core1[r, i]
// One warp handles 4 tokens simultaneously so each core1 float4 load is
// amortized across 4 tokens (core1 L1 traffic cut 4x).
// x is streamed with __ldcs (evict-first) to keep core1 resident in L1.
// ---------------------------------------------------------------------------
__global__ void __launch_bounds__(256) tt_stage1(const float* __restrict__ x,
                                                 const float* __restrict__ c1,
                                                 int tokens) {
    const int warp = threadIdx.x >> 5;
    const int lane = threadIdx.x & 31;
    const int token0 = (blockIdx.x * 8 + warp) * 4;
    if (token0 >= tokens) return;

    const float4* xp = reinterpret_cast<const float4*>(x) + (size_t)token0 * (IN_F / 4);
    const float4* cp = reinterpret_cast<const float4*>(c1);

    float acc[4][RANK];
#pragma unroll
    for (int t = 0; t < 4; t++)
#pragma unroll
        for (int r = 0; r < RANK; r++) acc[t][r] = 0.0f;

    // 1024 float4 per token row; 32 lanes -> 32 iterations
#pragma unroll 4
    for (int i = lane; i < IN_F / 4; i += 32) {
        float4 xv[4];
#pragma unroll
        for (int t = 0; t < 4; t++)
            xv[t] = __ldcs(xp + (size_t)t * (IN_F / 4) + i);
#pragma unroll
        for (int r = 0; r < RANK; r++) {
            float4 c = __ldg(cp + (size_t)r * (IN_F / 4) + i);
#pragma unroll
            for (int t = 0; t < 4; t++) {
                acc[t][r] += xv[t].x * c.x + xv[t].y * c.y
                           + xv[t].z * c.z + xv[t].w * c.w;
            }
        }
    }

    // Warp tree-reduce each of the 32 accumulators
#pragma unroll
    for (int t = 0; t < 4; t++)
#pragma unroll
        for (int r = 0; r < RANK; r++) {
            float v = acc[t][r];
#pragma unroll
            for (int off = 16; off; off >>= 1)
                v += __shfl_xor_sync(0xffffffffu, v, off);
            acc[t][r] = v;
        }

    if (lane == 0) {
#pragma unroll
        for (int t = 0; t < 4; t++)
#pragma unroll
            for (int r = 0; r < RANK; r++)
                g_t[(size_t)(token0 + t) * RANK + r] = acc[t][r];
    }
}

// ---------------------------------------------------------------------------
// Stage 2: y[tok, o] = bias[o] + sum_r t[tok, r] * core0[o, r]
// Block handles 32 tokens x all 4096 outputs. core0 coefficients for a
// thread's 4 consecutive outputs live in registers (read once per block);
// t is broadcast from 1 KB smem. Stores are STG.128, 512B/warp contiguous.
// ---------------------------------------------------------------------------
__global__ void __launch_bounds__(256) tt_stage2(const float* __restrict__ c0,
                                                 const float* __restrict__ bias,
                                                 float* __restrict__ y,
                                                 int tokens) {
    __shared__ float ts[32 * RANK];   // t for this block's 32 tokens (256 floats)
    const int tid = threadIdx.x;
    const int token0 = blockIdx.x * 32;

    ts[tid] = g_t[(size_t)token0 * RANK + tid];
    __syncthreads();

#pragma unroll
    for (int p = 0; p < 4; p++) {
        const int o = (p * 256 + tid) * 4;   // 4 consecutive outputs

        float4 ca[4], cb[4];
#pragma unroll
        for (int j = 0; j < 4; j++) {
            const float4* c = reinterpret_cast<const float4*>(c0 + (size_t)(o + j) * RANK);
            ca[j] = __ldg(c);
            cb[j] = __ldg(c + 1);
        }
        const float4 bv = __ldg(reinterpret_cast<const float4*>(bias + o));

        for (int tok = 0; tok < 32; tok++) {
            const float* tr = &ts[tok * RANK];
            const float t0 = tr[0], t1 = tr[1], t2 = tr[2], t3 = tr[3];
            const float t4 = tr[4], t5 = tr[5], t6 = tr[6], t7 = tr[7];

            float4 res;
            res.x = bv.x + ca[0].x * t0 + ca[0].y * t1 + ca[0].z * t2 + ca[0].w * t3
                         + cb[0].x * t4 + cb[0].y * t5 + cb[0].z * t6 + cb[0].w * t7;
            res.y = bv.y + ca[1].x * t0 + ca[1].y * t1 + ca[1].z * t2 + ca[1].w * t3
                         + cb[1].x * t4 + cb[1].y * t5 + cb[1].z * t6 + cb[1].w * t7;
            res.z = bv.z + ca[2].x * t0 + ca[2].y * t1 + ca[2].z * t2 + ca[2].w * t3
                         + cb[2].x * t4 + cb[2].y * t5 + cb[2].z * t6 + cb[2].w * t7;
            res.w = bv.w + ca[3].x * t0 + ca[3].y * t1 + ca[3].z * t2 + ca[3].w * t3
                         + cb[3].x * t4 + cb[3].y * t5 + cb[3].z * t6 + cb[3].w * t7;

            *reinterpret_cast<float4*>(y + (size_t)(token0 + tok) * OUT_F + o) = res;
        }
    }
}

extern "C" void kernel_launch(void* const* d_in, const int* in_sizes, int n_in,
                              void* d_out, int out_size) {
    const float* x    = (const float*)d_in[0];   // [TOKENS, IN_F]
    const float* c0   = (const float*)d_in[1];   // [1, OUT_F, RANK] -> [OUT_F, RANK]
    const float* c1   = (const float*)d_in[2];   // [RANK, IN_F, 1]  -> [RANK, IN_F]
    const float* bias = (const float*)d_in[3];   // [OUT_F]
    float* y = (float*)d_out;

    const int tokens = in_sizes[0] / IN_F;       // 8192

    // Stage 1: 8 warps/block * 4 tokens/warp = 32 tokens/block
    tt_stage1<<<tokens / 32, 256>>>(x, c1, tokens);
    // Stage 2: 32 tokens/block
    tt_stage2<<<tokens / 32, 256>>>(c0, bias, y, tokens);
}

// round 2
// speedup vs baseline: 1.0280x; 1.0280x over previous
#include <cuda_runtime.h>
#include <cuda_bf16.h>

#define IN_F   4096
#define OUT_F  4096
#define RANK   8
#define MAX_TOKENS 8192

// Intermediate t[tok][r] = x @ core1^T  (256 KB, lives in L2)
__device__ float g_t[MAX_TOKENS * RANK];

// ---------------------------------------------------------------------------
// Stage 1: t[tok, r] = sum_i x[tok, i] * core1[r, i]
// One warp handles 4 tokens simultaneously so each core1 float4 load is
// amortized across 4 tokens (core1 L1 traffic cut 4x).
// x is streamed with __ldcs (evict-first) to keep core1 resident in L1.
// ---------------------------------------------------------------------------
__global__ void __launch_bounds__(256) tt_stage1(const float* __restrict__ x,
                                                 const float* __restrict__ c1,
                                                 int tokens) {
    const int warp = threadIdx.x >> 5;
    const int lane = threadIdx.x & 31;
    const int token0 = (blockIdx.x * 8 + warp) * 4;
    if (token0 >= tokens) return;

    const float4* xp = reinterpret_cast<const float4*>(x) + (size_t)token0 * (IN_F / 4);
    const float4* cp = reinterpret_cast<const float4*>(c1);

    float acc[4][RANK];
#pragma unroll
    for (int t = 0; t < 4; t++)
#pragma unroll
        for (int r = 0; r < RANK; r++) acc[t][r] = 0.0f;

    // 1024 float4 per token row; 32 lanes -> 32 iterations
#pragma unroll 4
    for (int i = lane; i < IN_F / 4; i += 32) {
        float4 xv[4];
#pragma unroll
        for (int t = 0; t < 4; t++)
            xv[t] = __ldcs(xp + (size_t)t * (IN_F / 4) + i);
#pragma unroll
        for (int r = 0; r < RANK; r++) {
            float4 c = __ldg(cp + (size_t)r * (IN_F / 4) + i);
#pragma unroll
            for (int t = 0; t < 4; t++) {
                acc[t][r] += xv[t].x * c.x + xv[t].y * c.y
                           + xv[t].z * c.z + xv[t].w * c.w;
            }
        }
    }

    // Warp tree-reduce each of the 32 accumulators
#pragma unroll
    for (int t = 0; t < 4; t++)
#pragma unroll
        for (int r = 0; r < RANK; r++) {
            float v = acc[t][r];
#pragma unroll
            for (int off = 16; off; off >>= 1)
                v += __shfl_xor_sync(0xffffffffu, v, off);
            acc[t][r] = v;
        }

    if (lane == 0) {
#pragma unroll
        for (int t = 0; t < 4; t++)
#pragma unroll
            for (int r = 0; r < RANK; r++)
                g_t[(size_t)(token0 + t) * RANK + r] = acc[t][r];
    }
}

// ---------------------------------------------------------------------------
// Stage 2: y[tok, o] = bias[o] + sum_r t[tok, r] * core0[o, r]
// Block handles 32 tokens x all 4096 outputs. core0 coefficients for a
// thread's 4 consecutive outputs live in registers (read once per block);
// t is broadcast from 1 KB smem. Stores are STG.128, 512B/warp contiguous.
// ---------------------------------------------------------------------------
__global__ void __launch_bounds__(256) tt_stage2(const float* __restrict__ c0,
                                                 const float* __restrict__ bias,
                                                 float* __restrict__ y,
                                                 int tokens) {
    __shared__ float ts[32 * RANK];   // t for this block's 32 tokens (256 floats)
    const int tid = threadIdx.x;
    const int token0 = blockIdx.x * 32;

    ts[tid] = g_t[(size_t)token0 * RANK + tid];
    __syncthreads();

#pragma unroll
    for (int p = 0; p < 4; p++) {
        const int o = (p * 256 + tid) * 4;   // 4 consecutive outputs

        float4 ca[4], cb[4];
#pragma unroll
        for (int j = 0; j < 4; j++) {
            const float4* c = reinterpret_cast<const float4*>(c0 + (size_t)(o + j) * RANK);
            ca[j] = __ldg(c);
            cb[j] = __ldg(c + 1);
        }
        const float4 bv = __ldg(reinterpret_cast<const float4*>(bias + o));

        for (int tok = 0; tok < 32; tok++) {
            const float* tr = &ts[tok * RANK];
            const float t0 = tr[0], t1 = tr[1], t2 = tr[2], t3 = tr[3];
            const float t4 = tr[4], t5 = tr[5], t6 = tr[6], t7 = tr[7];

            float4 res;
            res.x = bv.x + ca[0].x * t0 + ca[0].y * t1 + ca[0].z * t2 + ca[0].w * t3
                         + cb[0].x * t4 + cb[0].y * t5 + cb[0].z * t6 + cb[0].w * t7;
            res.y = bv.y + ca[1].x * t0 + ca[1].y * t1 + ca[1].z * t2 + ca[1].w * t3
                         + cb[1].x * t4 + cb[1].y * t5 + cb[1].z * t6 + cb[1].w * t7;
            res.z = bv.z + ca[2].x * t0 + ca[2].y * t1 + ca[2].z * t2 + ca[2].w * t3
                         + cb[2].x * t4 + cb[2].y * t5 + cb[2].z * t6 + cb[2].w * t7;
            res.w = bv.w + ca[3].x * t0 + ca[3].y * t1 + ca[3].z * t2 + ca[3].w * t3
                         + cb[3].x * t4 + cb[3].y * t5 + cb[3].z * t6 + cb[3].w * t7;

            *reinterpret_cast<float4*>(y + (size_t)(token0 + tok) * OUT_F + o) = res;
        }
    }
}

extern "C" void kernel_launch(void* const* d_in, const int* in_sizes, int n_in,
                              void* d_out, int out_size) {
    const float* x    = (const float*)d_in[0];   // [TOKENS, IN_F]
    const float* c0   = (const float*)d_in[1];   // [1, OUT_F, RANK] -> [OUT_F, RANK]
    const float* c1   = (const float*)d_in[2];   // [RANK, IN_F, 1]  -> [RANK, IN_F]
    const float* bias = (const float*)d_in[3];   // [OUT_F]
    float* y = (float*)d_out;

    const int tokens = in_sizes[0] / IN_F;       // 8192

    // Stage 1: 8 warps/block * 4 tokens/warp = 32 tokens/block
    tt_stage1<<<tokens / 32, 256>>>(x, c1, tokens);
    // Stage 2: 32 tokens/block
    tt_stage2<<<tokens / 32, 256>>>(c0, bias, y, tokens);
}

// round 3
// speedup vs baseline: 1.1261x; 1.0954x over previous
#include <cuda_runtime.h>
#include <cuda_bf16.h>

#define IN_F   4096
#define OUT_F  4096
#define RANK   8
#define MAX_TOKENS 8192

// Intermediate t[tok][r] = x @ core1^T  (256 KB, lives in L2)
__device__ float g_t[MAX_TOKENS * RANK];

// ---------------------------------------------------------------------------
// Stage 1: t[tok, r] = sum_i x[tok, i] * core1[r, i]
// Block = 8 warps = 16 tokens. Each warp-pair owns 4 tokens; the two warps
// of a pair each reduce one half of IN_F (512 float4 each, 16 iterations).
// 512 blocks / 4096 warps -> ~2x the resident warps of round 1, halving
// exposed DRAM latency per warp. core1 stays L1-resident (__ldg), x streams
// with __ldcs (evict-first).
// ---------------------------------------------------------------------------
__global__ void __launch_bounds__(256) tt_stage1(const float* __restrict__ x,
                                                 const float* __restrict__ c1,
                                                 int tokens) {
    __shared__ float part[8][4][RANK];        // per-warp partial sums

    const int warp  = threadIdx.x >> 5;
    const int lane  = threadIdx.x & 31;
    const int group = warp >> 1;              // 0..3 : which 4-token group
    const int half  = warp & 1;               // 0/1  : which half of IN_F
    const int tokbase = blockIdx.x * 16;
    const int token0  = tokbase + group * 4;

    const float4* xp = reinterpret_cast<const float4*>(x)
                     + (size_t)token0 * (IN_F / 4) + half * 512;
    const float4* cp = reinterpret_cast<const float4*>(c1) + half * 512;

    float acc[4][RANK];
#pragma unroll
    for (int t = 0; t < 4; t++)
#pragma unroll
        for (int r = 0; r < RANK; r++) acc[t][r] = 0.0f;

    // 512 float4 per warp, 32 lanes -> 16 iterations
#pragma unroll 2
    for (int i = lane; i < 512; i += 32) {
        float4 xv[4];
#pragma unroll
        for (int t = 0; t < 4; t++)
            xv[t] = __ldcs(xp + (size_t)t * (IN_F / 4) + i);
#pragma unroll
        for (int r = 0; r < RANK; r++) {
            float4 c = __ldg(cp + (size_t)r * (IN_F / 4) + i);
#pragma unroll
            for (int t = 0; t < 4; t++) {
                acc[t][r] += xv[t].x * c.x + xv[t].y * c.y
                           + xv[t].z * c.z + xv[t].w * c.w;
            }
        }
    }

    // Warp tree-reduce each of the 32 accumulators
#pragma unroll
    for (int t = 0; t < 4; t++)
#pragma unroll
        for (int r = 0; r < RANK; r++) {
            float v = acc[t][r];
#pragma unroll
            for (int off = 16; off; off >>= 1)
                v += __shfl_xor_sync(0xffffffffu, v, off);
            acc[t][r] = v;
        }

    if (lane == 0) {
#pragma unroll
        for (int t = 0; t < 4; t++)
#pragma unroll
            for (int r = 0; r < RANK; r++)
                part[warp][t][r] = acc[t][r];
    }
    __syncthreads();

    // Combine the two half-row partials; 128 threads cover 16 tokens x 8 ranks
    if (threadIdx.x < 16 * RANK) {
        const int tl  = threadIdx.x >> 3;     // local token 0..15
        const int r   = threadIdx.x & 7;
        const int grp = tl >> 2;
        const int tt  = tl & 3;
        g_t[(size_t)(tokbase + tl) * RANK + r] =
            part[2 * grp][tt][r] + part[2 * grp + 1][tt][r];
    }
}

// ---------------------------------------------------------------------------
// Stage 2: y[tok, o] = bias[o] + sum_r t[tok, r] * core0[o, r]
// Grid = (OUT_F/1024) x (tokens/32) = 4 x 256 = 1024 blocks (4x round 1).
// Each thread owns 4 consecutive outputs (core0 coeffs in 32 registers,
// loaded once) and loops 32 tokens, broadcasting t from 1 KB smem.
// Stores are STG.128, 512B contiguous per warp.
// ---------------------------------------------------------------------------
__global__ void __launch_bounds__(256) tt_stage2(const float* __restrict__ c0,
                                                 const float* __restrict__ bias,
                                                 float* __restrict__ y,
                                                 int tokens) {
    __shared__ float ts[32 * RANK];           // t for this block's 32 tokens
    const int tid = threadIdx.x;
    const int token0 = blockIdx.y * 32;
    const int o = blockIdx.x * 1024 + tid * 4; // 4 consecutive outputs

    ts[tid] = g_t[(size_t)token0 * RANK + tid];

    float4 ca[4], cb[4];
#pragma unroll
    for (int j = 0; j < 4; j++) {
        const float4* c = reinterpret_cast<const float4*>(c0 + (size_t)(o + j) * RANK);
        ca[j] = __ldg(c);
        cb[j] = __ldg(c + 1);
    }
    const float4 bv = __ldg(reinterpret_cast<const float4*>(bias + o));

    __syncthreads();

#pragma unroll 4
    for (int tok = 0; tok < 32; tok++) {
        const float* tr = &ts[tok * RANK];
        const float t0 = tr[0], t1 = tr[1], t2 = tr[2], t3 = tr[3];
        const float t4 = tr[4], t5 = tr[5], t6 = tr[6], t7 = tr[7];

        float4 res;
        res.x = bv.x + ca[0].x * t0 + ca[0].y * t1 + ca[0].z * t2 + ca[0].w * t3
                     + cb[0].x * t4 + cb[0].y * t5 + cb[0].z * t6 + cb[0].w * t7;
        res.y = bv.y + ca[1].x * t0 + ca[1].y * t1 + ca[1].z * t2 + ca[1].w * t3
                     + cb[1].x * t4 + cb[1].y * t5 + cb[1].z * t6 + cb[1].w * t7;
        res.z = bv.z + ca[2].x * t0 + ca[2].y * t1 + ca[2].z * t2 + ca[2].w * t3
                     + cb[2].x * t4 + cb[2].y * t5 + cb[2].z * t6 + cb[2].w * t7;
        res.w = bv.w + ca[3].x * t0 + ca[3].y * t1 + ca[3].z * t2 + ca[3].w * t3
                     + cb[3].x * t4 + cb[3].y * t5 + cb[3].z * t6 + cb[3].w * t7;

        *reinterpret_cast<float4*>(y + (size_t)(token0 + tok) * OUT_F + o) = res;
    }
}

extern "C" void kernel_launch(void* const* d_in, const int* in_sizes, int n_in,
                              void* d_out, int out_size) {
    const float* x    = (const float*)d_in[0];   // [TOKENS, IN_F]
    const float* c0   = (const float*)d_in[1];   // [1, OUT_F, RANK] -> [OUT_F, RANK]
    const float* c1   = (const float*)d_in[2];   // [RANK, IN_F, 1]  -> [RANK, IN_F]
    const float* bias = (const float*)d_in[3];   // [OUT_F]
    float* y = (float*)d_out;

    const int tokens = in_sizes[0] / IN_F;       // 8192

    // Stage 1: 16 tokens / block (4 tokens per warp-pair, half-row per warp)
    tt_stage1<<<tokens / 16, 256>>>(x, c1, tokens);

    // Stage 2: 4 output chunks x 32-token groups = 1024 blocks
    dim3 g2(OUT_F / 1024, tokens / 32);
    tt_stage2<<<g2, 256>>>(c0, bias, y, tokens);
}